// round 16
// baseline (speedup 1.0000x reference)
#include <cuda_runtime.h>
#include <cuda_bf16.h>

// Problem constants (fixed by the reference)
#define BB 2
#define CC 64
#define HH 512
#define WW 512
#define HW (HH * WW)          // 262144
#define NN 4096
#define KK 5
#define NPAIR (BB * NN)       // 8192
#define INV_MAXDIST (1.0f / 724.07733f)
#define FEAT_THRESH_NOMATCH 16.0f
// fixed-point: fp = term * FP_SCALE, FP_SCALE = (1/24576) * 2^48 = 2^35/3
// finalize: out = (sum fp) * 2^-48
#define FP_SCALE (34359738368.0f / 3.0f)          // 1.1453246123e10
#define FP_INV   (1.0 / 281474976710656.0)        // 2^-48
#define QPTS 1024             // points per quarter
#define NTERMS (NPAIR * 6)    // 49152 independent loss terms
#define MATCH_BLOCKS 1536     // 1536 blocks x 8 warps x 4 groups = 49152

// Scratch (allocation-free rule: __device__ globals)
__device__ float g_fr[NPAIR * CC];      // compacted ref features   [b][i][c]
__device__ float g_fo[NPAIR * CC];      // compacted other features [b][i][c]
__device__ unsigned long long g_isum;   // fixed-point loss accumulator
__device__ unsigned int       g_ticket; // completion counter (blocks)

// sum-of-squared-differences over a float4 pair
__device__ __forceinline__ float ssd4(float4 a, float4 b) {
    float d0 = a.x - b.x, d1 = a.y - b.y, d2 = a.z - b.z, d3 = a.w - b.w;
    return d0 * d0 + d1 * d1 + d2 * d2 + d3 * d3;
}

// butterfly reduce within 8-lane groups (3 steps); every lane gets the sum
__device__ __forceinline__ float group8_sum(float v) {
    v += __shfl_xor_sync(0xFFFFFFFFu, v, 1, 8);
    v += __shfl_xor_sync(0xFFFFFFFFu, v, 2, 8);
    v += __shfl_xor_sync(0xFFFFFFFFu, v, 4, 8);
    return v;
}

// ---------------------------------------------------------------------------
// Kernel 1: fused block-local sort + gather. 128 blocks x 256 threads, one
// wave. Block (s, q, cc): set s (0,1=ref b0/b1; 2,3=oth b0/b1), quarter q,
// channel-chunk cc. Each block counting-sorts its quarter's 1024 points by y
// in SMEM (redundant across the 8 cc-blocks -- no inter-block dependency),
// then gathers warp<->32 sorted points in one plane (DRAM row locality).
// Results are id-indexed, so within-bucket permutation nondeterminism never
// reaches the output.
// ---------------------------------------------------------------------------
__global__ void __launch_bounds__(256) sortgather_kernel(
        const float* __restrict__ ref,
        const float* __restrict__ oth,
        const int* __restrict__ inds_ref,
        const int* __restrict__ inds_other) {
    __shared__ int lin_s[QPTS];       // 4 KB
    __shared__ int order_s[QPTS];     // 4 KB  packed (lin<<12 | global id)
    __shared__ int hist[512];
    __shared__ int offs[512];
    __shared__ int wsum[8];

    int tid  = threadIdx.x;
    int lane = tid & 31;
    int wib  = tid >> 5;              // warp in block (0..7)
    int bx   = blockIdx.x;
    int cc   = bx & 7;                // channel chunk (8): channels 8cc..8cc+7
    int q    = (bx >> 3) & 3;         // quarter
    int s    = bx >> 5;               // set
    int t = s >> 1, b = s & 1;

    if (bx == 0 && tid == 0) {        // reset accumulators for graph replay
        g_isum = 0ULL;
        g_ticket = 0u;
    }

    const int* inds = t ? inds_other : inds_ref;
    int i0 = q * QPTS;

    // ---- Phase 1: block-local counting sort of 1024 points by y ----
    hist[tid] = 0;
    hist[tid + 256] = 0;
    __syncthreads();

#pragma unroll
    for (int r = 0; r < 4; r++) {
        int il = tid + r * 256;           // local 0..1023
        int i  = i0 + il;
        int x  = inds[b * 2 * NN + i];
        int y  = inds[b * 2 * NN + NN + i];
        int lin = (y << 9) | x;           // 512*y + x
        lin_s[il] = lin;
        atomicAdd(&hist[y], 1);
    }
    __syncthreads();

    // scan 512 buckets with 256 threads (thread owns buckets 2t, 2t+1)
    int h0 = hist[2 * tid];
    int h1 = hist[2 * tid + 1];
    int psum = h0 + h1;
    int v = psum;
#pragma unroll
    for (int d = 1; d < 32; d <<= 1) {
        int u = __shfl_up_sync(0xFFFFFFFFu, v, d);
        if (lane >= d) v += u;
    }
    if (lane == 31) wsum[wib] = v;
    __syncthreads();
    if (tid < 32) {
        int u = (tid < 8) ? wsum[tid] : 0;
#pragma unroll
        for (int d = 1; d < 8; d <<= 1) {
            int x2 = __shfl_up_sync(0xFFFFFFFFu, u, d);
            if (lane >= d) u += x2;
        }
        if (tid < 8) wsum[tid] = u;
    }
    __syncthreads();
    int base = ((wib > 0) ? wsum[wib - 1] : 0) + (v - psum);
    offs[2 * tid]     = base;
    offs[2 * tid + 1] = base + h0;
    __syncthreads();

#pragma unroll
    for (int r = 0; r < 4; r++) {
        int il  = tid + r * 256;
        int lin = lin_s[il];
        int pos = atomicAdd(&offs[lin >> 9], 1);
        order_s[pos] = (lin << 12) | (i0 + il);
    }
    __syncthreads();

    // ---- Phase 2: gather. 64 slots = 2 channel-groups x 32 chunks ----
    const float* srcbase = t ? oth : ref;
    float* dstbase = t ? g_fo : g_fr;
#pragma unroll
    for (int slot = wib; slot < 64; slot += 8) {
        int cg    = 2 * cc + (slot >> 5);   // channel group 0..15
        int chunk = slot & 31;

        int packed = order_s[chunk * 32 + lane];
        int lin = packed >> 12;
        int id  = packed & 4095;

        const float* src = srcbase + (size_t)(b * CC + 4 * cg) * HW + lin;
        float v0 = __ldg(src + 0 * HW);
        float v1 = __ldg(src + 1 * HW);
        float v2 = __ldg(src + 2 * HW);
        float v3 = __ldg(src + 3 * HW);

        float* dst = dstbase + (size_t)((b << 12) | id) * CC + 4 * cg;
        *reinterpret_cast<float4*>(dst) = make_float4(v0, v1, v2, v3);
    }
}

// ---------------------------------------------------------------------------
// Kernel 2: match, term-parallel. 49152 independent loss terms (per pair:
// 1 match term + 5 negative terms), one 8-lane group per term, 4 groups per
// warp -> 1536 blocks x 256 threads (10.4 blocks/SM, balanced). Each group
// issues 4 independent float4 loads -> ~6x the in-flight loads of the
// pair-parallel version, hiding the L2/DRAM latency that bounded it.
// Each term is independently fixed-point quantized (deterministic: same
// inputs -> same rounding every replay). One atomic + ticket per block.
// ---------------------------------------------------------------------------
__global__ void __launch_bounds__(256) match_kernel(
        const float* __restrict__ weights,
        const int* __restrict__ inds_ref,
        const int* __restrict__ rand_inds,
        float* __restrict__ out) {
    __shared__ long long s_fp[32];
    int tid  = threadIdx.x;
    int lane = tid & 31;
    int wib  = tid >> 5;
    int grp  = lane >> 3;             // group in warp (0..3)
    int gl   = lane & 7;              // lane in group (0..7)
    int gid  = (blockIdx.x * 8 + wib) * 4 + grp;   // 0..49151
    int pair = gid / 6;
    int term = gid - pair * 6;        // 0 = match, 1..5 = negative k-1
    int b = pair >> 12;
    int i = pair & (NN - 1);

    // partner index: pair itself for the match term, rand_inds[j] otherwise
    int j = (term == 0) ? i : __ldg(rand_inds + (size_t)pair * KK + (term - 1));

    // 4 independent float4 loads (channels 8*gl .. 8*gl+7)
    const float4* frp = reinterpret_cast<const float4*>(
        g_fr + (size_t)pair * CC + 8 * gl);
    const float4* fpp = reinterpret_cast<const float4*>(
        g_fo + (size_t)(b * NN + j) * CC + 8 * gl);
    float4 fra = frp[0], frb = frp[1];
    float4 fpa = fpp[0], fpb = fpp[1];

    float ssd = group8_sum(ssd4(fra, fpa) + ssd4(frb, fpb));

    if (gl == 0) {
        float val;
        if (term == 0) {
            val = weights[b * NN + i] * fmaxf(ssd, 0.0f);
        } else {
            int xr = inds_ref[b * 2 * NN + i];
            int yr = inds_ref[b * 2 * NN + NN + i];
            float xj = (float)inds_ref[b * 2 * NN + j];
            float yj = (float)inds_ref[b * 2 * NN + NN + j];
            float dx = (float)xr - xj;
            float dy = (float)yr - yj;
            float dist = sqrtf(dx * dx + dy * dy);
            val = (-dist * INV_MAXDIST) * fminf(ssd, FEAT_THRESH_NOMATCH);
        }
        s_fp[wib * 4 + grp] = llrintf(val * FP_SCALE);
    }
    __syncthreads();

    if (tid == 0) {
        long long bsum = 0;
#pragma unroll
        for (int k = 0; k < 32; k++) bsum += s_fp[k];
        atomicAdd(&g_isum, (unsigned long long)bsum);
        __threadfence();
        unsigned int t = atomicAdd(&g_ticket, 1u);
        if (t == MATCH_BLOCKS - 1) {
            long long s = (long long)g_isum;
            out[0] = (float)((double)s * FP_INV);
        }
    }
}

extern "C" void kernel_launch(void* const* d_in, const int* in_sizes, int n_in,
                              void* d_out, int out_size) {
    const float* inputs_ref   = (const float*)d_in[0];
    const float* inputs_other = (const float*)d_in[1];
    const float* weights      = (const float*)d_in[2];
    const int*   inds_ref     = (const int*)d_in[3];
    const int*   inds_other   = (const int*)d_in[4];
    const int*   rand_inds    = (const int*)d_in[5];
    float* out = (float*)d_out;

    // 128 blocks: 4 sets x 4 quarters x 8 channel-chunks, one wave
    sortgather_kernel<<<128, 256>>>(inputs_ref, inputs_other,
                                    inds_ref, inds_other);
    match_kernel<<<MATCH_BLOCKS, 256>>>(weights, inds_ref, rand_inds, out);
}